// round 10
// baseline (speedup 1.0000x reference)
#include <cuda_runtime.h>
#include <cuda_bf16.h>
#include <math.h>
#include <stdint.h>

#define D 128
#define MAXS 65536
#define MAXN 8192

// ---------------- scratch (device globals — no runtime allocation)
__device__ float g_ztxt[MAXN * D];               // normalized text features (fp32, for k_img)
__device__ __nv_bfloat16 g_Tb[MAXN * D];         // normalized text features (bf16)
__device__ __nv_bfloat16 g_TbM[MAXN * D];        // col-masked bf16 text features (GEMM B)
__device__ __nv_bfloat16 g_Ab[MAXN * D];         // selected+normalized image rows (GEMM A)
__device__ float g_inv[MAXS];                    // 1/(||img||+1e-12)
__device__ unsigned long long g_seg[MAXN];       // packed (pot_bits<<32)|img_idx, atomicMin
__device__ double g_sum;

__device__ __forceinline__ uint32_t smem_u32(const void* p) {
    uint32_t a;
    asm("{ .reg .u64 t; cvta.to.shared.u64 t, %1; cvt.u32.u64 %0, t; }" : "=r"(a) : "l"(p));
    return a;
}

// ---------------- Phase 1: normalize text (warp/row) + fused scratch init
__global__ void k_norm_txt(const float* __restrict__ txt, int n) {
    int gtid = blockIdx.x * blockDim.x + threadIdx.x;
    if (gtid < n) g_seg[gtid] = ~0ull;
    if (gtid == 0) g_sum = 0.0;
    int w = gtid >> 5;
    int lane = threadIdx.x & 31;
    if (w >= n) return;
    float4 v = reinterpret_cast<const float4*>(txt + (size_t)w * D)[lane];
    float ss = v.x*v.x + v.y*v.y + v.z*v.z + v.w*v.w;
    #pragma unroll
    for (int o = 16; o > 0; o >>= 1) ss += __shfl_xor_sync(0xffffffffu, ss, o);
    float inv = 1.0f / (sqrtf(ss) + 1e-12f);
    float4 r = make_float4(v.x*inv, v.y*inv, v.z*inv, v.w*inv);
    reinterpret_cast<float4*>(g_ztxt + (size_t)w * D)[lane] = r;
    __nv_bfloat162 b0 = __floats2bfloat162_rn(r.x, r.y);
    __nv_bfloat162 b1 = __floats2bfloat162_rn(r.z, r.w);
    __nv_bfloat162* dst = reinterpret_cast<__nv_bfloat162*>(g_Tb + (size_t)w * D + lane * 4);
    dst[0] = b0; dst[1] = b1;
}

// ---------------- Phase 2: tp logit + segmented argmin (half-warp per image)
__global__ void k_img(const float* __restrict__ img, const int* __restrict__ key,
                      const float* __restrict__ sp, const float* __restrict__ bp, int s) {
    int hw = (blockIdx.x * blockDim.x + threadIdx.x) >> 4;   // half-warp id = image id
    int hl = threadIdx.x & 15;
    if (hw >= s) return;
    const float4* vi = reinterpret_cast<const float4*>(img + (size_t)hw * D);
    float4 v0 = vi[hl], v1 = vi[hl + 16];
    int k = key[hw];
    const float4* ti = reinterpret_cast<const float4*>(g_ztxt + (size_t)k * D);
    float4 t0 = ti[hl], t1 = ti[hl + 16];
    float ss = v0.x*v0.x + v0.y*v0.y + v0.z*v0.z + v0.w*v0.w
             + v1.x*v1.x + v1.y*v1.y + v1.z*v1.z + v1.w*v1.w;
    float dt = v0.x*t0.x + v0.y*t0.y + v0.z*t0.z + v0.w*t0.w
             + v1.x*t1.x + v1.y*t1.y + v1.z*t1.z + v1.w*t1.w;
    #pragma unroll
    for (int o = 8; o > 0; o >>= 1) {
        ss += __shfl_xor_sync(0xffffffffu, ss, o);
        dt += __shfl_xor_sync(0xffffffffu, dt, o);
    }
    if (hl == 0) {
        float inv = 1.0f / (sqrtf(ss) + 1e-12f);
        g_inv[hw] = inv;
        float tp = fmaf(dt * inv, *sp, *bp);
        float t = -tp;
        float pot = fmaxf(t, 0.0f) + log1pf(expf(-fabsf(t)));
        unsigned long long pk =
            ((unsigned long long)__float_as_uint(pot) << 32) | (unsigned)hw;
        atomicMin(&g_seg[k], pk);
    }
}

// ---------------- Phase 3: gather best image -> bf16 A rows; write col-masked B
__global__ void k_gather(const float* __restrict__ img, int n) {
    int w = (blockIdx.x * blockDim.x + threadIdx.x) >> 5;
    int lane = threadIdx.x & 31;
    if (w >= n) return;
    unsigned long long sv = g_seg[w];
    bool valid = (sv != ~0ull);
    float4 o = make_float4(0.f, 0.f, 0.f, 0.f);
    if (valid) {
        unsigned best = (unsigned)(sv & 0xffffffffu);
        float inv = g_inv[best];
        float4 v = reinterpret_cast<const float4*>(img + (size_t)best * D)[lane];
        o = make_float4(v.x*inv, v.y*inv, v.z*inv, v.w*inv);
    }
    __nv_bfloat162 b0 = __floats2bfloat162_rn(o.x, o.y);
    __nv_bfloat162 b1 = __floats2bfloat162_rn(o.z, o.w);
    __nv_bfloat162* dst = reinterpret_cast<__nv_bfloat162*>(g_Ab + (size_t)w * D + lane * 4);
    dst[0] = b0; dst[1] = b1;
    uint2 tv = make_uint2(0u, 0u);
    if (valid)
        tv = reinterpret_cast<const uint2*>(g_Tb + (size_t)w * D)[lane];
    reinterpret_cast<uint2*>(g_TbM + (size_t)w * D)[lane] = tv;
}

// ---------------- Phase 4: bf16 mma.sync GEMM, A-resident supertile (1x4 B tiles),
//                  double-buffered B-tile prefetch + register-level fragment pipeline
__device__ __forceinline__ void ldsm4(uint32_t* r, uint32_t addr) {
    asm volatile("ldmatrix.sync.aligned.m8n8.x4.shared.b16 {%0,%1,%2,%3}, [%4];"
                 : "=r"(r[0]), "=r"(r[1]), "=r"(r[2]), "=r"(r[3]) : "r"(addr));
}
__device__ __forceinline__ void mma16816(float* c, const uint32_t* a, const uint32_t* b) {
    asm volatile("mma.sync.aligned.m16n8k16.row.col.f32.bf16.bf16.f32 "
                 "{%0,%1,%2,%3}, {%4,%5,%6,%7}, {%8,%9}, {%0,%1,%2,%3};"
                 : "+f"(c[0]), "+f"(c[1]), "+f"(c[2]), "+f"(c[3])
                 : "r"(a[0]), "r"(a[1]), "r"(a[2]), "r"(a[3]), "r"(b[0]), "r"(b[1]));
}
__device__ __forceinline__ uint32_t sw_off(int row, int cb) {
    return (uint32_t)(row * 256 + (((cb ^ (row & 7)) & 15) << 4));
}
__device__ __forceinline__ void cp16(uint32_t dst, const void* src) {
    asm volatile("cp.async.cg.shared.global [%0], [%1], 16;" :: "r"(dst), "l"(src));
}
#define NT 4

__global__ void __launch_bounds__(256, 2)
k_gemm_loss(const float* __restrict__ sp, const float* __restrict__ bp) {
    extern __shared__ __align__(1024) char smem[];
    const uint32_t A_OFF = 0u;
    const uint32_t B_OFF0 = 32768u, B_OFF1 = 65536u;
    float* swred = (float*)(smem + 98304);
    uint32_t sb = smem_u32(smem);

    int tid = threadIdx.x, wid = tid >> 5, lane = tid & 31;
    int bm = blockIdx.y;
    int bng = blockIdx.x * NT;
    int wm = (wid & 3) << 5;
    int wn = (wid >> 2) << 6;
    int lrow = lane & 15;
    int lcb  = lane >> 4;
    uint32_t r7 = (uint32_t)(lrow & 7);

    // per-warp base addresses (swizzle term added per load: ((cb^r7)<<4), cb=ks*2+lcb)
    uint32_t aRow0 = sb + A_OFF + (uint32_t)(wm + lrow) * 256u;
    uint32_t aRow1 = aRow0 + 16u * 256u;
    uint32_t bRow[4];
    #pragma unroll
    for (int nb = 0; nb < 4; nb++)
        bRow[nb] = (uint32_t)(wn + nb * 16 + lrow) * 256u;

    // prologue: group0 = {A, B0}; group1 = {B1}
    {
        const uint4* Ag = reinterpret_cast<const uint4*>(g_Ab + (size_t)bm * 128 * D);
        const uint4* Bg = reinterpret_cast<const uint4*>(g_TbM + (size_t)bng * 128 * D);
        #pragma unroll
        for (int i = 0; i < 8; i++) {
            int ch = tid + i * 256;
            int row = ch >> 4, cb = ch & 15;
            uint32_t off = sw_off(row, cb);
            cp16(sb + A_OFF + off, Ag + ch);
            cp16(sb + B_OFF0 + off, Bg + ch);
        }
        asm volatile("cp.async.commit_group;");
        const uint4* Bg1 = reinterpret_cast<const uint4*>(g_TbM + (size_t)(bng + 1) * 128 * D);
        #pragma unroll
        for (int i = 0; i < 8; i++) {
            int ch = tid + i * 256;
            uint32_t off = sw_off(ch >> 4, ch & 15);
            cp16(sb + B_OFF1 + off, Bg1 + ch);
        }
        asm volatile("cp.async.commit_group;");
    }

    const float scale = *sp, bias = *bp;
    const float sl = scale * 1.44269504f, bl = bias * 1.44269504f;
    int qr = lane >> 2;
    int qc = (lane & 3) << 1;
    float lsum = 0.f;

    #pragma unroll
    for (int t = 0; t < NT; t++) {
        if (t < NT - 2)      asm volatile("cp.async.wait_group 1;" ::: "memory");
        else                 asm volatile("cp.async.wait_group 0;" ::: "memory");
        __syncthreads();

        uint32_t bbase = sb + ((t & 1) ? B_OFF1 : B_OFF0);

        float acc[2][8][4];
        #pragma unroll
        for (int i = 0; i < 2; i++)
            #pragma unroll
            for (int j = 0; j < 8; j++)
                #pragma unroll
                for (int k = 0; k < 4; k++) acc[i][j][k] = 0.f;

        // register-pipelined fragment loop: 32 steps = 8 ks x 4 nb
        uint32_t af[2][2][4];     // [ks&1][row-frag][4]
        uint32_t bf[2][4];        // [step&1][4]
        {
            uint32_t sw0 = (uint32_t)((lcb ^ (int)r7) << 4);   // ks=0
            ldsm4(af[0][0], aRow0 + sw0);
            ldsm4(af[0][1], aRow1 + sw0);
            ldsm4(bf[0], bbase + bRow[0] + sw0);
        }
        #pragma unroll
        for (int step = 0; step < 32; step++) {
            const int ks = step >> 2, nb = step & 3;
            const int abuf = ks & 1, bbuf = step & 1;
            if (step < 31) {
                const int ns = step + 1;
                const int nks = ns >> 2, nnb = ns & 3;
                uint32_t swn = (uint32_t)(((nks * 2 + lcb) ^ (int)r7) << 4);
                if (nnb == 0) {
                    ldsm4(af[nks & 1][0], aRow0 + swn);
                    ldsm4(af[nks & 1][1], aRow1 + swn);
                }
                ldsm4(bf[ns & 1], bbase + bRow[nnb] + swn);
            }
            uint32_t b0[2] = { bf[bbuf][0], bf[bbuf][2] };
            uint32_t b1[2] = { bf[bbuf][1], bf[bbuf][3] };
            mma16816(acc[0][nb * 2 + 0], af[abuf][0], b0);
            mma16816(acc[0][nb * 2 + 1], af[abuf][0], b1);
            mma16816(acc[1][nb * 2 + 0], af[abuf][1], b0);
            mma16816(acc[1][nb * 2 + 1], af[abuf][1], b1);
        }
        __syncthreads();   // all warps done reading this B buffer

        // prefetch tile t+2 into the buffer just freed
        if (t + 2 < NT) {
            const uint4* Bg = reinterpret_cast<const uint4*>(
                g_TbM + (size_t)(bng + t + 2) * 128 * D);
            uint32_t dstb = sb + ((t & 1) ? B_OFF1 : B_OFF0);
            #pragma unroll
            for (int i = 0; i < 8; i++) {
                int ch = tid + i * 256;
                uint32_t off = sw_off(ch >> 4, ch & 15);
                cp16(dstb + off, Bg + ch);
            }
            asm volatile("cp.async.commit_group;");
        }

        // fused epilogue for this tile (overlaps the prefetch)
        int bn = bng + t;
        if (bm != bn) {
            #pragma unroll
            for (int am = 0; am < 2; am++)
                #pragma unroll
                for (int na = 0; na < 8; na++)
                    #pragma unroll
                    for (int k = 0; k < 4; k++) {
                        float dv = acc[am][na][k];
                        float x2 = fmaf(dv, sl, bl);
                        float r; asm("ex2.approx.f32 %0, %1;" : "=f"(r) : "f"(x2));
                        lsum = fmaf(r, fmaf(r, -0.5f, 1.0f), lsum);  // += softplus(x)
                    }
        } else {
            #pragma unroll
            for (int am = 0; am < 2; am++) {
                #pragma unroll
                for (int na = 0; na < 8; na++) {
                    #pragma unroll
                    for (int k = 0; k < 4; k++) {
                        int ci = k >> 1, cj = k & 1;
                        int lr = wm + am * 16 + qr + ci * 8;
                        int lc = wn + na * 8 + qc + cj;
                        float dv = acc[am][na][k];
                        float x2 = fmaf(dv, sl, bl);
                        float r; asm("ex2.approx.f32 %0, %1;" : "=f"(r) : "f"(x2));
                        lsum = fmaf(r, fmaf(r, -0.5f, 1.0f), lsum);
                        if (lr == lc)              // softplus(-x) = softplus(x) - x
                            lsum -= fmaf(dv, scale, bias);
                    }
                }
            }
        }
    }

    #pragma unroll
    for (int o = 16; o > 0; o >>= 1) lsum += __shfl_xor_sync(0xffffffffu, lsum, o);
    if (lane == 0) swred[wid] = lsum;
    __syncthreads();
    if (wid == 0) {
        float v = (lane < 8) ? swred[lane] : 0.f;
        #pragma unroll
        for (int o = 4; o > 0; o >>= 1) v += __shfl_xor_sync(0xffffffffu, v, o);
        if (lane == 0) atomicAdd(&g_sum, (double)v);
    }
}

// ---------------- Phase 5: finalize (parallel valid count + analytic correction)
__global__ void k_final(float* out, const float* __restrict__ bp, int n) {
    __shared__ int sred[256];
    int tid = threadIdx.x;
    int cnt = 0;
    for (int i = tid; i < n; i += 256)
        if (g_seg[i] != ~0ull) cnt++;
    cnt += __shfl_xor_sync(0xffffffffu, cnt, 16);
    cnt += __shfl_xor_sync(0xffffffffu, cnt, 8);
    cnt += __shfl_xor_sync(0xffffffffu, cnt, 4);
    cnt += __shfl_xor_sync(0xffffffffu, cnt, 2);
    cnt += __shfl_xor_sync(0xffffffffu, cnt, 1);
    if ((tid & 31) == 0) sred[tid >> 5] = cnt;
    __syncthreads();
    if (tid == 0) {
        int nv = 0;
        #pragma unroll
        for (int i = 0; i < 8; i++) nv += sred[i];
        float bias = *bp;
        int n_inv = n - nv;
        float bl = bias * 1.44269504f;
        float r0; asm("ex2.approx.f32 %0, %1;" : "=f"(r0) : "f"(bl));
        float p0 = fmaf(r0, -0.5f, 1.0f);      // must match GEMM epilogue series
        double c0 = (double)r0 * (double)p0;
        double npairs_inv = (double)n * (double)n - (double)nv * (double)nv;
        double corr = npairs_inv * c0 - (double)n_inv * (double)bias;
        int dnv = nv < 1 ? 1 : nv;
        out[0] = (float)((g_sum - corr) / (double)dnv);
    }
}

extern "C" void kernel_launch(void* const* d_in, const int* in_sizes, int n_in,
                              void* d_out, int out_size) {
    const float* img = (const float*)d_in[0];
    const float* txt = (const float*)d_in[1];
    const int*   key = (const int*)d_in[2];
    const float* sc  = (const float*)d_in[3];
    const float* bi  = (const float*)d_in[4];
    int s = in_sizes[2];          // 65536
    int n = in_sizes[1] / D;      // 8192

    const int SMEM_BYTES = 98304 + 64;
    cudaFuncSetAttribute(k_gemm_loss, cudaFuncAttributeMaxDynamicSharedMemorySize, SMEM_BYTES);

    k_norm_txt<<<(n * 32 + 255) / 256, 256>>>(txt, n);
    k_img<<<(s * 16 + 255) / 256, 256>>>(img, key, sc, bi, s);
    k_gather<<<(n * 32 + 255) / 256, 256>>>(img, n);
    dim3 grid(n / 128 / NT, n / 128);
    k_gemm_loss<<<grid, 256, SMEM_BYTES>>>(sc, bi);
    k_final<<<1, 256>>>((float*)d_out, bi, n);
}

// round 11
// speedup vs baseline: 1.0436x; 1.0436x over previous
#include <cuda_runtime.h>
#include <cuda_bf16.h>
#include <math.h>
#include <stdint.h>

#define D 128
#define MAXS 65536
#define MAXN 8192

// ---------------- scratch (device globals — no runtime allocation)
__device__ float g_ztxt[MAXN * D];               // normalized text features (fp32, for k_img)
__device__ __nv_bfloat16 g_Tb[MAXN * D];         // normalized text features (bf16)
__device__ __nv_bfloat16 g_TbM[MAXN * D];        // col-masked bf16 text features (GEMM B)
__device__ __nv_bfloat16 g_Ab[MAXN * D];         // selected+normalized image rows (GEMM A)
__device__ float g_inv[MAXS];                    // 1/(||img||+1e-12)
__device__ unsigned long long g_seg[MAXN];       // packed (pot_bits<<32)|img_idx, atomicMin
__device__ double g_sum;

__device__ __forceinline__ uint32_t smem_u32(const void* p) {
    uint32_t a;
    asm("{ .reg .u64 t; cvta.to.shared.u64 t, %1; cvt.u32.u64 %0, t; }" : "=r"(a) : "l"(p));
    return a;
}

// ---------------- Phase 1: normalize text (warp/row) + fused scratch init
__global__ void k_norm_txt(const float* __restrict__ txt, int n) {
    int gtid = blockIdx.x * blockDim.x + threadIdx.x;
    if (gtid < n) g_seg[gtid] = ~0ull;
    if (gtid == 0) g_sum = 0.0;
    int w = gtid >> 5;
    int lane = threadIdx.x & 31;
    if (w >= n) return;
    float4 v = reinterpret_cast<const float4*>(txt + (size_t)w * D)[lane];
    float ss = v.x*v.x + v.y*v.y + v.z*v.z + v.w*v.w;
    #pragma unroll
    for (int o = 16; o > 0; o >>= 1) ss += __shfl_xor_sync(0xffffffffu, ss, o);
    float inv = 1.0f / (sqrtf(ss) + 1e-12f);
    float4 r = make_float4(v.x*inv, v.y*inv, v.z*inv, v.w*inv);
    reinterpret_cast<float4*>(g_ztxt + (size_t)w * D)[lane] = r;
    __nv_bfloat162 b0 = __floats2bfloat162_rn(r.x, r.y);
    __nv_bfloat162 b1 = __floats2bfloat162_rn(r.z, r.w);
    __nv_bfloat162* dst = reinterpret_cast<__nv_bfloat162*>(g_Tb + (size_t)w * D + lane * 4);
    dst[0] = b0; dst[1] = b1;
}

// ---------------- Phase 2: tp logit + segmented argmin (half-warp per image)
__global__ void k_img(const float* __restrict__ img, const int* __restrict__ key,
                      const float* __restrict__ sp, const float* __restrict__ bp, int s) {
    int hw = (blockIdx.x * blockDim.x + threadIdx.x) >> 4;   // half-warp id = image id
    int hl = threadIdx.x & 15;
    if (hw >= s) return;
    const float4* vi = reinterpret_cast<const float4*>(img + (size_t)hw * D);
    float4 v0 = vi[hl], v1 = vi[hl + 16];
    int k = key[hw];
    const float4* ti = reinterpret_cast<const float4*>(g_ztxt + (size_t)k * D);
    float4 t0 = ti[hl], t1 = ti[hl + 16];
    float ss = v0.x*v0.x + v0.y*v0.y + v0.z*v0.z + v0.w*v0.w
             + v1.x*v1.x + v1.y*v1.y + v1.z*v1.z + v1.w*v1.w;
    float dt = v0.x*t0.x + v0.y*t0.y + v0.z*t0.z + v0.w*t0.w
             + v1.x*t1.x + v1.y*t1.y + v1.z*t1.z + v1.w*t1.w;
    #pragma unroll
    for (int o = 8; o > 0; o >>= 1) {
        ss += __shfl_xor_sync(0xffffffffu, ss, o);
        dt += __shfl_xor_sync(0xffffffffu, dt, o);
    }
    if (hl == 0) {
        float inv = 1.0f / (sqrtf(ss) + 1e-12f);
        g_inv[hw] = inv;
        float tp = fmaf(dt * inv, *sp, *bp);
        float t = -tp;
        float pot = fmaxf(t, 0.0f) + log1pf(expf(-fabsf(t)));
        unsigned long long pk =
            ((unsigned long long)__float_as_uint(pot) << 32) | (unsigned)hw;
        atomicMin(&g_seg[k], pk);
    }
}

// ---------------- Phase 3: gather best image -> bf16 A rows; write col-masked B
__global__ void k_gather(const float* __restrict__ img, int n) {
    int w = (blockIdx.x * blockDim.x + threadIdx.x) >> 5;
    int lane = threadIdx.x & 31;
    if (w >= n) return;
    unsigned long long sv = g_seg[w];
    bool valid = (sv != ~0ull);
    float4 o = make_float4(0.f, 0.f, 0.f, 0.f);
    if (valid) {
        unsigned best = (unsigned)(sv & 0xffffffffu);
        float inv = g_inv[best];
        float4 v = reinterpret_cast<const float4*>(img + (size_t)best * D)[lane];
        o = make_float4(v.x*inv, v.y*inv, v.z*inv, v.w*inv);
    }
    __nv_bfloat162 b0 = __floats2bfloat162_rn(o.x, o.y);
    __nv_bfloat162 b1 = __floats2bfloat162_rn(o.z, o.w);
    __nv_bfloat162* dst = reinterpret_cast<__nv_bfloat162*>(g_Ab + (size_t)w * D + lane * 4);
    dst[0] = b0; dst[1] = b1;
    uint2 tv = make_uint2(0u, 0u);
    if (valid)
        tv = reinterpret_cast<const uint2*>(g_Tb + (size_t)w * D)[lane];
    reinterpret_cast<uint2*>(g_TbM + (size_t)w * D)[lane] = tv;
}

// ---------------- Phase 4: bf16 mma.sync GEMM, A-resident supertile (1x4 B tiles),
//                  double-buffered B prefetch, precomputed addressing, lean epilogue
__device__ __forceinline__ void ldsm4(uint32_t* r, uint32_t addr) {
    asm volatile("ldmatrix.sync.aligned.m8n8.x4.shared.b16 {%0,%1,%2,%3}, [%4];"
                 : "=r"(r[0]), "=r"(r[1]), "=r"(r[2]), "=r"(r[3]) : "r"(addr));
}
__device__ __forceinline__ void mma16816(float* c, const uint32_t* a, const uint32_t* b) {
    asm volatile("mma.sync.aligned.m16n8k16.row.col.f32.bf16.bf16.f32 "
                 "{%0,%1,%2,%3}, {%4,%5,%6,%7}, {%8,%9}, {%0,%1,%2,%3};"
                 : "+f"(c[0]), "+f"(c[1]), "+f"(c[2]), "+f"(c[3])
                 : "r"(a[0]), "r"(a[1]), "r"(a[2]), "r"(a[3]), "r"(b[0]), "r"(b[1]));
}
__device__ __forceinline__ uint32_t sw_off(int row, int cb) {
    return (uint32_t)(row * 256 + (((cb ^ (row & 7)) & 15) << 4));
}
__device__ __forceinline__ void cp16(uint32_t dst, const void* src) {
    asm volatile("cp.async.cg.shared.global [%0], [%1], 16;" :: "r"(dst), "l"(src));
}
#define NT 4

__global__ void __launch_bounds__(256, 2)
k_gemm_loss(const float* __restrict__ sp, const float* __restrict__ bp) {
    extern __shared__ __align__(1024) char smem[];
    const uint32_t A_OFF = 0u;
    const uint32_t B_OFF0 = 32768u, B_OFF1 = 65536u;
    float* swred = (float*)(smem + 98304);
    uint32_t sb = smem_u32(smem);

    int tid = threadIdx.x, wid = tid >> 5, lane = tid & 31;
    int bm = blockIdx.y;
    int bng = blockIdx.x * NT;
    int wm = (wid & 3) << 5;
    int wn = (wid >> 2) << 6;
    int lrow = lane & 15;
    int lcb  = lane >> 4;
    int r7 = lrow & 7;

    // precomputed addressing: addr = rowbase + swk[ks]
    uint32_t swk[8];
    #pragma unroll
    for (int ks = 0; ks < 8; ks++)
        swk[ks] = (uint32_t)((((ks * 2 + lcb) ^ r7) & 15) << 4);
    uint32_t aR0 = sb + A_OFF + (uint32_t)(wm + lrow) * 256u;
    uint32_t aR1 = aR0 + 4096u;
    uint32_t rowOff[4];
    #pragma unroll
    for (int nb = 0; nb < 4; nb++)
        rowOff[nb] = (uint32_t)(wn + nb * 16 + lrow) * 256u;

    // prologue: group0 = {A, B0}; group1 = {B1}
    {
        const uint4* Ag = reinterpret_cast<const uint4*>(g_Ab + (size_t)bm * 128 * D);
        const uint4* Bg = reinterpret_cast<const uint4*>(g_TbM + (size_t)bng * 128 * D);
        #pragma unroll
        for (int i = 0; i < 8; i++) {
            int ch = tid + i * 256;
            int row = ch >> 4, cb = ch & 15;
            uint32_t off = sw_off(row, cb);
            cp16(sb + A_OFF + off, Ag + ch);
            cp16(sb + B_OFF0 + off, Bg + ch);
        }
        asm volatile("cp.async.commit_group;");
        const uint4* Bg1 = reinterpret_cast<const uint4*>(g_TbM + (size_t)(bng + 1) * 128 * D);
        #pragma unroll
        for (int i = 0; i < 8; i++) {
            int ch = tid + i * 256;
            uint32_t off = sw_off(ch >> 4, ch & 15);
            cp16(sb + B_OFF1 + off, Bg1 + ch);
        }
        asm volatile("cp.async.commit_group;");
    }

    const float scale = *sp, bias = *bp;
    const float sl = scale * 1.44269504f, bl = bias * 1.44269504f;
    int qr = lane >> 2;
    int qc = (lane & 3) << 1;
    float lsum = 0.f;

    #pragma unroll
    for (int t = 0; t < NT; t++) {
        if (t < NT - 2)      asm volatile("cp.async.wait_group 1;" ::: "memory");
        else                 asm volatile("cp.async.wait_group 0;" ::: "memory");
        __syncthreads();

        uint32_t bbase = sb + ((t & 1) ? B_OFF1 : B_OFF0);
        uint32_t bR[4];
        #pragma unroll
        for (int nb = 0; nb < 4; nb++) bR[nb] = bbase + rowOff[nb];

        float acc[2][8][4];
        #pragma unroll
        for (int i = 0; i < 2; i++)
            #pragma unroll
            for (int j = 0; j < 8; j++)
                #pragma unroll
                for (int k = 0; k < 4; k++) acc[i][j][k] = 0.f;

        #pragma unroll
        for (int ks = 0; ks < 8; ks++) {
            uint32_t sw = swk[ks];
            uint32_t af[2][4];
            ldsm4(af[0], aR0 + sw);
            ldsm4(af[1], aR1 + sw);
            #pragma unroll
            for (int nb = 0; nb < 4; nb++) {
                uint32_t bf[4];
                ldsm4(bf, bR[nb] + sw);
                uint32_t b0[2] = { bf[0], bf[2] };
                uint32_t b1[2] = { bf[1], bf[3] };
                mma16816(acc[0][nb * 2 + 0], af[0], b0);
                mma16816(acc[0][nb * 2 + 1], af[0], b1);
                mma16816(acc[1][nb * 2 + 0], af[1], b0);
                mma16816(acc[1][nb * 2 + 1], af[1], b1);
            }
        }
        __syncthreads();   // all warps done reading this B buffer

        // prefetch tile t+2 into the buffer just freed
        if (t + 2 < NT) {
            const uint4* Bg = reinterpret_cast<const uint4*>(
                g_TbM + (size_t)(bng + t + 2) * 128 * D);
            uint32_t dstb = sb + ((t & 1) ? B_OFF1 : B_OFF0);
            #pragma unroll
            for (int i = 0; i < 8; i++) {
                int ch = tid + i * 256;
                uint32_t off = sw_off(ch >> 4, ch & 15);
                cp16(dstb + off, Bg + ch);
            }
            asm volatile("cp.async.commit_group;");
        }

        // lean fused epilogue: softplus(x) ~= r = 2^(sl*dv+bl); diag: softplus(-x)=r-x
        int bn = bng + t;
        if (bm != bn) {
            #pragma unroll
            for (int am = 0; am < 2; am++)
                #pragma unroll
                for (int na = 0; na < 8; na++)
                    #pragma unroll
                    for (int k = 0; k < 4; k++) {
                        float x2 = fmaf(acc[am][na][k], sl, bl);
                        float r; asm("ex2.approx.f32 %0, %1;" : "=f"(r) : "f"(x2));
                        lsum += r;
                    }
        } else {
            #pragma unroll
            for (int am = 0; am < 2; am++) {
                #pragma unroll
                for (int na = 0; na < 8; na++) {
                    #pragma unroll
                    for (int k = 0; k < 4; k++) {
                        int ci = k >> 1, cj = k & 1;
                        int lr = wm + am * 16 + qr + ci * 8;
                        int lc = wn + na * 8 + qc + cj;
                        float dv = acc[am][na][k];
                        float x2 = fmaf(dv, sl, bl);
                        float r; asm("ex2.approx.f32 %0, %1;" : "=f"(r) : "f"(x2));
                        lsum += r;
                        if (lr == lc)              // softplus(-x) = softplus(x) - x
                            lsum -= fmaf(dv, scale, bias);
                    }
                }
            }
        }
    }

    #pragma unroll
    for (int o = 16; o > 0; o >>= 1) lsum += __shfl_xor_sync(0xffffffffu, lsum, o);
    if (lane == 0) swred[wid] = lsum;
    __syncthreads();
    if (wid == 0) {
        float v = (lane < 8) ? swred[lane] : 0.f;
        #pragma unroll
        for (int o = 4; o > 0; o >>= 1) v += __shfl_xor_sync(0xffffffffu, v, o);
        if (lane == 0) atomicAdd(&g_sum, (double)v);
    }
}

// ---------------- Phase 5: finalize (parallel valid count + analytic correction)
__global__ void k_final(float* out, const float* __restrict__ bp, int n) {
    __shared__ int sred[256];
    int tid = threadIdx.x;
    int cnt = 0;
    for (int i = tid; i < n; i += 256)
        if (g_seg[i] != ~0ull) cnt++;
    cnt += __shfl_xor_sync(0xffffffffu, cnt, 16);
    cnt += __shfl_xor_sync(0xffffffffu, cnt, 8);
    cnt += __shfl_xor_sync(0xffffffffu, cnt, 4);
    cnt += __shfl_xor_sync(0xffffffffu, cnt, 2);
    cnt += __shfl_xor_sync(0xffffffffu, cnt, 1);
    if ((tid & 31) == 0) sred[tid >> 5] = cnt;
    __syncthreads();
    if (tid == 0) {
        int nv = 0;
        #pragma unroll
        for (int i = 0; i < 8; i++) nv += sred[i];
        float bias = *bp;
        int n_inv = n - nv;
        float bl = bias * 1.44269504f;
        float r0; asm("ex2.approx.f32 %0, %1;" : "=f"(r0) : "f"(bl));
        // every invalid pair contributes plain r0; invalid diagonal adds -bias
        double c0 = (double)r0;
        double npairs_inv = (double)n * (double)n - (double)nv * (double)nv;
        double corr = npairs_inv * c0 - (double)n_inv * (double)bias;
        int dnv = nv < 1 ? 1 : nv;
        out[0] = (float)((g_sum - corr) / (double)dnv);
    }
}

extern "C" void kernel_launch(void* const* d_in, const int* in_sizes, int n_in,
                              void* d_out, int out_size) {
    const float* img = (const float*)d_in[0];
    const float* txt = (const float*)d_in[1];
    const int*   key = (const int*)d_in[2];
    const float* sc  = (const float*)d_in[3];
    const float* bi  = (const float*)d_in[4];
    int s = in_sizes[2];          // 65536
    int n = in_sizes[1] / D;      // 8192

    const int SMEM_BYTES = 98304 + 64;
    cudaFuncSetAttribute(k_gemm_loss, cudaFuncAttributeMaxDynamicSharedMemorySize, SMEM_BYTES);

    k_norm_txt<<<(n * 32 + 255) / 256, 256>>>(txt, n);
    k_img<<<(s * 16 + 255) / 256, 256>>>(img, key, sc, bi, s);
    k_gather<<<(n * 32 + 255) / 256, 256>>>(img, n);
    dim3 grid(n / 128 / NT, n / 128);
    k_gemm_loss<<<grid, 256, SMEM_BYTES>>>(sc, bi);
    k_final<<<1, 256>>>((float*)d_out, bi, n);
}